// round 1
// baseline (speedup 1.0000x reference)
#include <cuda_runtime.h>

// Problem constants
#define Bb 16
#define Nn 64
#define Hh 256
#define Tt 5
#define Ee 8
#define ROWS (Bb*Nn*Nn)      // 16384 (b,i,j) rows
#define BNH  (Bb*Nn*Hh)      // 262144

// ---- device scratch (no allocations allowed) ----
__device__ float g_prop [BNH];
__device__ float g_msg  [Tt*BNH];      // msg_t for all timesteps, 21 MB (L2-resident)
__device__ float g_Wc   [Hh*Hh];       // img_fc_w @ w1[H:2H]
__device__ float g_fi2v [Bb*Hh];
__device__ float g_fsslv[Bb*Hh];
__device__ float g_biasb[Bb*Hh];       // per-batch effective bias into hidden
__device__ int   g_rows [ROWS];
__device__ int   g_count;

// ============================================================
// Generic small SGEMM: C[M,N] = A[M,K] @ B[K,N] + bias
// BM=32, BN=64, BK=32, 256 threads, 2x4 per thread.
// Requires K%32==0, N%4==0.
// ============================================================
__global__ __launch_bounds__(256) void sgemm_kernel(
    const float* __restrict__ A, const float* __restrict__ Bm,
    const float* __restrict__ bias, float* __restrict__ C,
    int M, int N, int K)
{
    __shared__ float As[32][33];
    __shared__ float Bs[32][68];
    int m0 = blockIdx.x * 32, n0 = blockIdx.y * 64;
    int tid = threadIdx.x;
    int tx = tid & 15, ty = tid >> 4;        // 16x16 thread grid
    float acc[2][4] = {};

    for (int k0 = 0; k0 < K; k0 += 32) {
        #pragma unroll
        for (int p = 0; p < 4; p++) {
            int lin = p*256 + tid; int r = lin >> 5, kk = lin & 31;
            int gr = m0 + r;
            As[r][kk] = (gr < M) ? A[(size_t)gr*K + k0 + kk] : 0.f;
        }
        #pragma unroll
        for (int p = 0; p < 2; p++) {
            int lin = p*256 + tid; int kk = lin >> 4, n4 = lin & 15;
            float4 v = *(const float4*)&Bm[(size_t)(k0+kk)*N + n0 + n4*4];
            *(float4*)&Bs[kk][n4*4] = v;
        }
        __syncthreads();
        #pragma unroll
        for (int k = 0; k < 32; k++) {
            float a0 = As[ty*2+0][k];
            float a1 = As[ty*2+1][k];
            float4 b4 = *(float4*)&Bs[k][tx*4];
            acc[0][0] += a0*b4.x; acc[0][1] += a0*b4.y; acc[0][2] += a0*b4.z; acc[0][3] += a0*b4.w;
            acc[1][0] += a1*b4.x; acc[1][1] += a1*b4.y; acc[1][2] += a1*b4.z; acc[1][3] += a1*b4.w;
        }
        __syncthreads();
    }
    #pragma unroll
    for (int q = 0; q < 2; q++) {
        int gr = m0 + ty*2 + q;
        if (gr < M) {
            #pragma unroll
            for (int c = 0; c < 4; c++) {
                int gc = n0 + tx*4 + c;
                float v = acc[q][c];
                if (bias) v += bias[gc];
                C[(size_t)gr*N + gc] = v;
            }
        }
    }
}

// ============================================================
// Scan aggregation: agg[b,i,h] = sum_j mask[b,i,j]*relu(mi+mj)*mj
//                   prop[b,i,h] += relu(mi + agg)
// grid: B*N blocks of 256 threads (one thread per h)
// ============================================================
__global__ __launch_bounds__(256) void agg_kernel(int t, const int* __restrict__ mask)
{
    int bi = blockIdx.x;                 // b*64 + i
    int b  = bi >> 6;
    int h  = threadIdx.x;
    __shared__ int msk[64];
    if (h < 64) msk[h] = mask[bi*64 + h];
    __syncthreads();

    const float* msgb = g_msg + (size_t)(t*Bb + b) * Nn * Hh;
    float mi = msgb[(bi & 63)*Hh + h];
    float acc = 0.f;
    #pragma unroll 8
    for (int j = 0; j < 64; j++) {
        if (msk[j]) {
            float mj = __ldg(&msgb[j*Hh + h]);
            acc += fmaxf(mi + mj, 0.f) * mj;
        }
    }
    g_prop[(size_t)bi*Hh + h] += fmaxf(mi + acc, 0.f);
}

// ============================================================
// Per-batch effective bias:
// biasb[b,n] = b1[n] + bimg@w1[H:2H] + fi2v[b]@w1[2H:3H] + fsslv[b]@w1[3H:4H]
// ============================================================
__global__ __launch_bounds__(256) void biask_kernel(
    const float* __restrict__ b1, const float* __restrict__ bimg,
    const float* __restrict__ w1)
{
    int b = blockIdx.x, n = threadIdx.x;
    float s = b1[n];
    const float* f2 = g_fi2v  + b*256;
    const float* f3 = g_fsslv + b*256;
    for (int h = 0; h < 256; h++) {
        s += bimg[h] * w1[(256+h)*256 + n];
        s += f2[h]   * w1[(512+h)*256 + n];
        s += f3[h]   * w1[(768+h)*256 + n];
    }
    g_biasb[b*256 + n] = s;
}

// ============================================================
// Reset + compaction + output zero-fill
// ============================================================
__global__ void reset_kernel() { g_count = 0; }

__global__ __launch_bounds__(256) void compact_kernel(
    const int* __restrict__ mask, float* __restrict__ out)
{
    int r = blockIdx.x * 256 + threadIdx.x;   // 0..16383
    float4 z = make_float4(0.f, 0.f, 0.f, 0.f);
    float4* o = (float4*)(out + (size_t)r * 8);
    o[0] = z; o[1] = z;
    if (mask[r] != 0) {
        int p = atomicAdd(&g_count, 1);
        g_rows[p] = r;
    }
}

// ============================================================
// Fused final kernel (active rows only):
//   A[row, 0:256]   = maxpool row = relu(max_t(msg_t[b,i,:]+msg_t[b,j,:]))  (on the fly)
//   A[row, 256:512] = feat_img_1[b,i,j,:]
//   hidden = relu(A @ [w1[0:H]; Wc] + biasb[b])
//   out[row,:] = hidden @ w2 + b2
// BM=32, BN=256 (full), BK=32, 256 threads, 4x8 per thread.
// ============================================================
__global__ __launch_bounds__(256) void fuse_kernel(
    const float* __restrict__ fimg1, const float* __restrict__ w1,
    const float* __restrict__ w2,    const float* __restrict__ b2,
    float* __restrict__ out)
{
    __shared__ float As[32][33];
    __shared__ float Bs[32*256];          // reused as hidden[32][256] after mainloop
    __shared__ float w2s[256*8];
    __shared__ float b2s[8];
    __shared__ int rRow[32], rB[32], rI[32], rJ[32], rValid[32];

    int cnt = g_count;
    int m0  = blockIdx.x * 32;
    if (m0 >= cnt) return;
    int tid = threadIdx.x;

    if (tid < 32) {
        int idx = m0 + tid;
        int cl  = (idx < cnt) ? idx : (cnt - 1);
        int row = g_rows[cl];
        rRow[tid] = row;
        rValid[tid] = (idx < cnt);
        rB[tid] = row >> 12;
        rI[tid] = (row >> 6) & 63;
        rJ[tid] = row & 63;
    }
    for (int p = tid; p < 2048; p += 256) w2s[p] = w2[p];
    if (tid < 8) b2s[tid] = b2[tid];
    __syncthreads();

    int tx = tid & 31, ty = tid >> 5;     // 32 col-groups x 8 row-groups
    float acc[4][8] = {};

    for (int k0 = 0; k0 < 512; k0 += 32) {
        // --- B tile: stacked weights [w1[0:256] ; Wc] ---
        const float* Bsrc = (k0 < 256) ? (w1 + (size_t)k0*256)
                                       : (g_Wc + (size_t)(k0-256)*256);
        #pragma unroll
        for (int p = 0; p < 8; p++) {
            int lin = p*256 + tid; int kk = lin >> 6, n4 = lin & 63;
            *(float4*)&Bs[kk*256 + n4*4] = *(const float4*)&Bsrc[kk*256 + n4*4];
        }
        // --- A tile: fused maxpool (k<256) or feat_img_1 (k>=256) ---
        #pragma unroll
        for (int p = 0; p < 4; p++) {
            int lin = p*256 + tid; int r = lin >> 5, kk = lin & 31;
            int k = k0 + kk;
            float v;
            if (k < 256) {
                int b = rB[r], i = rI[r], j = rJ[r];
                const float* mi = g_msg + ((size_t)b*Nn + i)*Hh + k;
                const float* mj = g_msg + ((size_t)b*Nn + j)*Hh + k;
                float m = -1e30f;
                #pragma unroll
                for (int t = 0; t < Tt; t++)
                    m = fmaxf(m, mi[(size_t)t*BNH] + mj[(size_t)t*BNH]);
                v = fmaxf(m, 0.f);
            } else {
                v = fimg1[(size_t)rRow[r]*256 + (k - 256)];
            }
            As[r][kk] = v;
        }
        __syncthreads();
        #pragma unroll
        for (int k = 0; k < 32; k++) {
            float a[4];
            #pragma unroll
            for (int q = 0; q < 4; q++) a[q] = As[ty*4+q][k];
            float4 bv0 = *(float4*)&Bs[k*256 + tx*8];
            float4 bv1 = *(float4*)&Bs[k*256 + tx*8 + 4];
            #pragma unroll
            for (int q = 0; q < 4; q++) {
                acc[q][0] += a[q]*bv0.x; acc[q][1] += a[q]*bv0.y;
                acc[q][2] += a[q]*bv0.z; acc[q][3] += a[q]*bv0.w;
                acc[q][4] += a[q]*bv1.x; acc[q][5] += a[q]*bv1.y;
                acc[q][6] += a[q]*bv1.z; acc[q][7] += a[q]*bv1.w;
            }
        }
        __syncthreads();
    }

    // hidden = relu(acc + biasb[b]) into Bs (safe: synced after last k-tile)
    #pragma unroll
    for (int q = 0; q < 4; q++) {
        int r = ty*4 + q;
        const float* bb = g_biasb + rB[r]*256;
        #pragma unroll
        for (int c = 0; c < 8; c++) {
            int col = tx*8 + c;
            Bs[r*256 + col] = fmaxf(acc[q][c] + __ldg(&bb[col]), 0.f);
        }
    }
    __syncthreads();

    // epilogue: out[row, e] = hidden[row,:] @ w2[:,e] + b2[e]
    int r = tid >> 3, e = tid & 7;
    if (rValid[r]) {
        float s = b2s[e];
        const float* hrow = &Bs[r*256];
        #pragma unroll 8
        for (int h = 0; h < 256; h++) s += hrow[h] * w2s[h*8 + e];
        out[(size_t)rRow[r]*8 + e] = s;
    }
}

// ============================================================
extern "C" void kernel_launch(void* const* d_in, const int* in_sizes, int n_in,
                              void* d_out, int out_size)
{
    const float* feat_body    = (const float*)d_in[0];
    const float* feat_img_1   = (const float*)d_in[1];
    const float* feat_img_2   = (const float*)d_in[2];
    const float* feat_img_ssl = (const float*)d_in[3];
    const int*   full_mask    = (const int*)  d_in[4];
    const float* img_fc_w     = (const float*)d_in[5];
    const float* img_fc_b     = (const float*)d_in[6];
    const float* node_fc_w    = (const float*)d_in[7];
    const float* node_fc_b    = (const float*)d_in[8];
    const float* edge_fc_w1   = (const float*)d_in[9];
    const float* edge_fc_b1   = (const float*)d_in[10];
    const float* edge_fc_w2   = (const float*)d_in[11];
    const float* edge_fc_b2   = (const float*)d_in[12];
    float* out = (float*)d_out;

    void *pv;
    float *p_prop, *p_msg, *p_Wc, *p_fi2v, *p_fsslv;
    cudaGetSymbolAddress(&pv, g_prop);  p_prop  = (float*)pv;
    cudaGetSymbolAddress(&pv, g_msg);   p_msg   = (float*)pv;
    cudaGetSymbolAddress(&pv, g_Wc);    p_Wc    = (float*)pv;
    cudaGetSymbolAddress(&pv, g_fi2v);  p_fi2v  = (float*)pv;
    cudaGetSymbolAddress(&pv, g_fsslv); p_fsslv = (float*)pv;

    reset_kernel<<<1, 1>>>();
    compact_kernel<<<ROWS/256, 256>>>(full_mask, out);

    // prop0 = feat_body @ img_fc_w + img_fc_b
    sgemm_kernel<<<dim3(32, 4), 256>>>(feat_body, img_fc_w, img_fc_b, p_prop,
                                       Bb*Nn, Hh, Hh);
    // scan: msg_t = prop @ W_t + b_t ; prop += relu(msg + agg)
    for (int t = 0; t < Tt; t++) {
        sgemm_kernel<<<dim3(32, 4), 256>>>(p_prop, node_fc_w + (size_t)t*Hh*Hh,
                                           node_fc_b + t*Hh,
                                           p_msg + (size_t)t*BNH, Bb*Nn, Hh, Hh);
        if (t < Tt - 1) agg_kernel<<<Bb*Nn, 256>>>(t, full_mask);
    }

    // folded weights / biases (independent of scan)
    sgemm_kernel<<<dim3(8, 4), 256>>>(img_fc_w, edge_fc_w1 + (size_t)Hh*Hh,
                                      nullptr, p_Wc, Hh, Hh, Hh);
    sgemm_kernel<<<dim3(1, 4), 256>>>(feat_img_2, img_fc_w, img_fc_b, p_fi2v,
                                      Bb, Hh, Hh);
    sgemm_kernel<<<dim3(1, 4), 256>>>(feat_img_ssl, img_fc_w, img_fc_b, p_fsslv,
                                      Bb, Hh, Hh);
    biask_kernel<<<Bb, 256>>>(edge_fc_b1, img_fc_b, edge_fc_w1);

    // fused maxpool + double GEMM + epilogue over active rows
    fuse_kernel<<<ROWS/32, 256>>>(feat_img_1, edge_fc_w1, edge_fc_w2,
                                  edge_fc_b2, out);
}

// round 2
// speedup vs baseline: 1.1836x; 1.1836x over previous
#include <cuda_runtime.h>
#include <cstdint>

#define Bb 16
#define Nn 64
#define Hh 256
#define Tt 5
#define Ee 8
#define ROWS (Bb*Nn*Nn)      // 16384
#define BNH  (Bb*Nn*Hh)      // 262144

typedef unsigned long long ull;

// ---- device scratch ----
__device__ float g_prop [BNH];
__device__ float g_msg  [Tt*BNH];
__device__ float g_Wc   [Hh*Hh];
__device__ float g_fi2v [Bb*Hh];
__device__ float g_fsslv[Bb*Hh];
__device__ float g_biasb[Bb*Hh];
__device__ int   g_rows [ROWS];
__device__ int   g_count;

// ---- packed f32x2 helpers (rt=2 per SMSP but 2 MACs/lane -> 128 MAC/cyc/SM) ----
__device__ __forceinline__ ull pack2(float lo, float hi) {
    ull r; asm("mov.b64 %0, {%1,%2};" : "=l"(r) : "f"(lo), "f"(hi)); return r;
}
__device__ __forceinline__ void fma2(ull& d, ull a, ull b) {
    asm("fma.rn.f32x2 %0, %1, %2, %0;" : "+l"(d) : "l"(a), "l"(b));
}
__device__ __forceinline__ void unpack2(ull v, float& lo, float& hi) {
    asm("mov.b64 {%0,%1}, %2;" : "=f"(lo), "=f"(hi) : "l"(v));
}

// ---- cp.async helpers ----
__device__ __forceinline__ uint32_t sptr(const void* p) {
    return (uint32_t)__cvta_generic_to_shared(p);
}
__device__ __forceinline__ void cpa16(uint32_t dst, const void* src, int szbytes) {
    asm volatile("cp.async.ca.shared.global [%0], [%1], 16, %2;"
                 :: "r"(dst), "l"(src), "r"(szbytes));
}
#define CP_COMMIT() asm volatile("cp.async.commit_group;")
template<int N> __device__ __forceinline__ void cp_wait() {
    asm volatile("cp.async.wait_group %0;" :: "n"(N));
}

// ============================================================
// GEMM: C[M,256] = A[M,K] @ W[K,256] (+bias)
// BM=32, BN=64, BK=32, 256 threads, 2-stage cp.async pipeline,
// 2x4 per thread, packed f32x2 FMA.
// ============================================================
__global__ __launch_bounds__(256) void gemm_kernel(
    const float* __restrict__ A, const float* __restrict__ W,
    const float* __restrict__ bias, float* __restrict__ C,
    int M, int K)
{
    __shared__ __align__(16) float AS[2][32][36];
    __shared__ __align__(16) float BS[2][32][64];
    int m0 = blockIdx.x * 32, n0 = blockIdx.y * 64;
    int tid = threadIdx.x;

    // A stage copy: 32 rows x 32 floats = 256 x 16B chunks (1/thread)
    int ar = tid >> 3, ac = tid & 7;
    // B stage copy: 32 rows x 64 floats = 512 chunks (2/thread)
    int bk0 = tid >> 4, bc0 = tid & 15;

    auto issue = [&](int s, int k0) {
        bool aok = (m0 + ar) < M;
        const float* asrc = A + (size_t)(aok ? (m0 + ar) : 0) * K + k0 + ac*4;
        cpa16(sptr(&AS[s][ar][ac*4]), asrc, aok ? 16 : 0);
        #pragma unroll
        for (int q = 0; q < 2; q++) {
            int kk = bk0 + q*16;
            cpa16(sptr(&BS[s][kk][bc0*4]), W + (size_t)(k0+kk)*256 + n0 + bc0*4, 16);
        }
        CP_COMMIT();
    };

    int tx = tid & 15, ty = tid >> 4;       // 16 col-groups x 16 row-groups
    ull acc[2][2] = {};

    issue(0, 0);
    int nt = K >> 5;
    for (int t = 0; t < nt; t++) {
        if (t + 1 < nt) { issue((t+1)&1, (t+1)*32); cp_wait<1>(); }
        else            { cp_wait<0>(); }
        __syncthreads();
        int s = t & 1;
        #pragma unroll
        for (int k = 0; k < 32; k++) {
            float a0 = AS[s][ty*2+0][k];
            float a1 = AS[s][ty*2+1][k];
            float4 b = *(float4*)&BS[s][k][tx*4];
            ull bp0 = pack2(b.x, b.y), bp1 = pack2(b.z, b.w);
            ull aa0 = pack2(a0, a0),   aa1 = pack2(a1, a1);
            fma2(acc[0][0], aa0, bp0); fma2(acc[0][1], aa0, bp1);
            fma2(acc[1][0], aa1, bp0); fma2(acc[1][1], aa1, bp1);
        }
        __syncthreads();
    }

    #pragma unroll
    for (int q = 0; q < 2; q++) {
        int gr = m0 + ty*2 + q;
        if (gr < M) {
            float v[4];
            unpack2(acc[q][0], v[0], v[1]);
            unpack2(acc[q][1], v[2], v[3]);
            #pragma unroll
            for (int c = 0; c < 4; c++) {
                int gc = n0 + tx*4 + c;
                float o = v[c];
                if (bias) o += bias[gc];
                C[(size_t)gr*256 + gc] = o;
            }
        }
    }
}

// ============================================================
// Scan aggregation (unchanged logic)
// ============================================================
__global__ __launch_bounds__(256) void agg_kernel(int t, const int* __restrict__ mask)
{
    int bi = blockIdx.x;
    int b  = bi >> 6;
    int h  = threadIdx.x;
    __shared__ int msk[64];
    if (h < 64) msk[h] = mask[bi*64 + h];
    __syncthreads();

    const float* msgb = g_msg + (size_t)(t*Bb + b) * Nn * Hh;
    float mi = msgb[(bi & 63)*Hh + h];
    float acc = 0.f;
    #pragma unroll 8
    for (int j = 0; j < 64; j++) {
        if (msk[j]) {
            float mj = __ldg(&msgb[j*Hh + h]);
            acc += fmaxf(mi + mj, 0.f) * mj;
        }
    }
    g_prop[(size_t)bi*Hh + h] += fmaxf(mi + acc, 0.f);
}

// ============================================================
// Per-batch effective bias (wider grid than R1: 16x4 blocks)
// ============================================================
__global__ __launch_bounds__(256) void biask_kernel(
    const float* __restrict__ b1, const float* __restrict__ bimg,
    const float* __restrict__ w1)
{
    int b = blockIdx.x;
    int n = blockIdx.y*64 + (threadIdx.x & 63);
    int part = threadIdx.x >> 6;            // 0..3
    __shared__ float red[4][64];
    const float* f2 = g_fi2v  + b*256;
    const float* f3 = g_fsslv + b*256;
    float s = 0.f;
    for (int h = part; h < 256; h += 4) {
        s += bimg[h] * __ldg(&w1[(256+h)*256 + n]);
        s += f2[h]   * __ldg(&w1[(512+h)*256 + n]);
        s += f3[h]   * __ldg(&w1[(768+h)*256 + n]);
    }
    red[part][threadIdx.x & 63] = s;
    __syncthreads();
    if (part == 0) {
        int l = threadIdx.x & 63;
        g_biasb[b*256 + n] = b1[n] + red[0][l] + red[1][l] + red[2][l] + red[3][l];
    }
}

// ============================================================
// Reset + compaction + output zero-fill
// ============================================================
__global__ void reset_kernel() { g_count = 0; }

__global__ __launch_bounds__(256) void compact_kernel(
    const int* __restrict__ mask, float* __restrict__ out)
{
    int r = blockIdx.x * 256 + threadIdx.x;
    float4 z = make_float4(0.f, 0.f, 0.f, 0.f);
    float4* o = (float4*)(out + (size_t)r * 8);
    o[0] = z; o[1] = z;
    if (mask[r] != 0) {
        int p = atomicAdd(&g_count, 1);
        g_rows[p] = r;
    }
}

// ============================================================
// Fused final kernel over active rows.
// BM=64, BN=256 (full), BK=16, 256 threads, 8x8/thread packed FMA.
//   A[r,0:256]   = relu(max_t(msg_t[b,i,:]+msg_t[b,j,:]))  (generated)
//   A[r,256:512] = feat_img_1[b,i,j,:]
//   hidden = relu(A @ [w1a ; Wc] + biasb[b]);  out = hidden @ w2 + b2
// Epilogue: register-resident w2, warp-shuffle reduction.
// ============================================================
__global__ __launch_bounds__(256) void fuse_kernel(
    const float* __restrict__ fimg1, const float* __restrict__ w1,
    const float* __restrict__ w2,    const float* __restrict__ b2,
    float* __restrict__ out)
{
    __shared__ __align__(16) float As[16][68];    // [k][r]
    __shared__ __align__(16) float Bs[16][256];   // [k][n]
    __shared__ int sRow[64], sBI[64], sBJ[64], sB[64];

    int cnt = g_count;
    int m0  = blockIdx.x * 64;
    if (m0 >= cnt) return;
    int tid = threadIdx.x;

    if (tid < 64) {
        int idx = m0 + tid;
        int cl  = (idx < cnt) ? idx : (cnt - 1);
        int row = g_rows[cl];
        int b = row >> 12, i = (row >> 6) & 63, j = row & 63;
        sRow[tid] = row;
        sB[tid]   = b;
        sBI[tid]  = (b*64 + i) * 256;
        sBJ[tid]  = (b*64 + j) * 256;
    }
    __syncthreads();

    int tx = tid & 31, ty = tid >> 5;   // 32 col-groups(8 cols) x 8 row-groups(8 rows)
    ull acc[8][4];
    #pragma unroll
    for (int q = 0; q < 8; q++)
        #pragma unroll
        for (int c = 0; c < 4; c++) acc[q][c] = 0ULL;

    for (int k0 = 0; k0 < 512; k0 += 16) {
        // B tile
        const float* Bsrc = (k0 < 256) ? (w1 + (size_t)k0*256)
                                       : (g_Wc + (size_t)(k0-256)*256);
        #pragma unroll
        for (int p = 0; p < 4; p++) {
            int lin = p*256 + tid; int kk = lin >> 6, c = lin & 63;
            *(float4*)&Bs[kk][c*4] = *(const float4*)&Bsrc[kk*256 + c*4];
        }
        // A tile
        if (k0 < 256) {
            #pragma unroll
            for (int p = 0; p < 4; p++) {
                int lin = p*256 + tid; int r = lin >> 4, kk = lin & 15;
                int k = k0 + kk;
                const float* mi = g_msg + sBI[r] + k;
                const float* mj = g_msg + sBJ[r] + k;
                float m = mi[0] + mj[0];
                #pragma unroll
                for (int t = 1; t < Tt; t++)
                    m = fmaxf(m, mi[(size_t)t*BNH] + mj[(size_t)t*BNH]);
                As[kk][r] = fmaxf(m, 0.f);
            }
        } else {
            #pragma unroll
            for (int p = 0; p < 4; p++) {
                int lin = p*256 + tid; int r = lin >> 4, kk = lin & 15;
                As[kk][r] = __ldg(&fimg1[(size_t)sRow[r]*256 + (k0-256) + kk]);
            }
        }
        __syncthreads();
        #pragma unroll
        for (int k = 0; k < 16; k++) {
            float4 b0 = *(float4*)&Bs[k][tx*8];
            float4 b1 = *(float4*)&Bs[k][tx*8 + 4];
            ull bp0 = pack2(b0.x,b0.y), bp1 = pack2(b0.z,b0.w);
            ull bp2 = pack2(b1.x,b1.y), bp3 = pack2(b1.z,b1.w);
            float4 a0 = *(float4*)&As[k][ty*8];
            float4 a1 = *(float4*)&As[k][ty*8 + 4];
            float av[8] = {a0.x,a0.y,a0.z,a0.w,a1.x,a1.y,a1.z,a1.w};
            #pragma unroll
            for (int q = 0; q < 8; q++) {
                ull aa = pack2(av[q], av[q]);
                fma2(acc[q][0], aa, bp0); fma2(acc[q][1], aa, bp1);
                fma2(acc[q][2], aa, bp2); fma2(acc[q][3], aa, bp3);
            }
        }
        __syncthreads();
    }

    // Preload this lane's w2 rows into registers (cols tx*8..tx*8+7)
    float w2r[8][8];
    #pragma unroll
    for (int c = 0; c < 8; c++) {
        float4 u0 = __ldg((const float4*)&w2[(tx*8+c)*8]);
        float4 u1 = __ldg((const float4*)&w2[(tx*8+c)*8 + 4]);
        w2r[c][0]=u0.x; w2r[c][1]=u0.y; w2r[c][2]=u0.z; w2r[c][3]=u0.w;
        w2r[c][4]=u1.x; w2r[c][5]=u1.y; w2r[c][6]=u1.z; w2r[c][7]=u1.w;
    }

    // Epilogue: bias+relu, multiply w2, warp-reduce, store.
    #pragma unroll
    for (int q = 0; q < 8; q++) {
        int r = ty*8 + q;
        const float* bb = g_biasb + sB[r]*256 + tx*8;
        float h[8];
        unpack2(acc[q][0], h[0], h[1]);
        unpack2(acc[q][1], h[2], h[3]);
        unpack2(acc[q][2], h[4], h[5]);
        unpack2(acc[q][3], h[6], h[7]);
        float pe[8] = {0,0,0,0,0,0,0,0};
        #pragma unroll
        for (int c = 0; c < 8; c++) {
            float hv = fmaxf(h[c] + __ldg(&bb[c]), 0.f);
            #pragma unroll
            for (int e = 0; e < 8; e++) pe[e] += hv * w2r[c][e];
        }
        #pragma unroll
        for (int off = 16; off > 0; off >>= 1)
            #pragma unroll
            for (int e = 0; e < 8; e++)
                pe[e] += __shfl_xor_sync(0xffffffffu, pe[e], off);
        if (tx == 0 && (m0 + r) < cnt) {
            int row = sRow[r];
            #pragma unroll
            for (int e = 0; e < 8; e++)
                out[(size_t)row*8 + e] = pe[e] + __ldg(&b2[e]);
        }
    }
}

// ============================================================
extern "C" void kernel_launch(void* const* d_in, const int* in_sizes, int n_in,
                              void* d_out, int out_size)
{
    const float* feat_body    = (const float*)d_in[0];
    const float* feat_img_1   = (const float*)d_in[1];
    const float* feat_img_2   = (const float*)d_in[2];
    const float* feat_img_ssl = (const float*)d_in[3];
    const int*   full_mask    = (const int*)  d_in[4];
    const float* img_fc_w     = (const float*)d_in[5];
    const float* img_fc_b     = (const float*)d_in[6];
    const float* node_fc_w    = (const float*)d_in[7];
    const float* node_fc_b    = (const float*)d_in[8];
    const float* edge_fc_w1   = (const float*)d_in[9];
    const float* edge_fc_b1   = (const float*)d_in[10];
    const float* edge_fc_w2   = (const float*)d_in[11];
    const float* edge_fc_b2   = (const float*)d_in[12];
    float* out = (float*)d_out;

    void *pv;
    float *p_prop, *p_msg, *p_Wc, *p_fi2v, *p_fsslv;
    cudaGetSymbolAddress(&pv, g_prop);  p_prop  = (float*)pv;
    cudaGetSymbolAddress(&pv, g_msg);   p_msg   = (float*)pv;
    cudaGetSymbolAddress(&pv, g_Wc);    p_Wc    = (float*)pv;
    cudaGetSymbolAddress(&pv, g_fi2v);  p_fi2v  = (float*)pv;
    cudaGetSymbolAddress(&pv, g_fsslv); p_fsslv = (float*)pv;

    reset_kernel<<<1, 1>>>();
    compact_kernel<<<ROWS/256, 256>>>(full_mask, out);

    // prop0 = feat_body @ img_fc_w + img_fc_b
    gemm_kernel<<<dim3(32, 4), 256>>>(feat_body, img_fc_w, img_fc_b, p_prop,
                                      Bb*Nn, Hh);
    // scan
    for (int t = 0; t < Tt; t++) {
        gemm_kernel<<<dim3(32, 4), 256>>>(p_prop, node_fc_w + (size_t)t*Hh*Hh,
                                          node_fc_b + t*Hh,
                                          p_msg + (size_t)t*BNH, Bb*Nn, Hh);
        if (t < Tt - 1) agg_kernel<<<Bb*Nn, 256>>>(t, full_mask);
    }

    // folded weights / per-batch bias
    gemm_kernel<<<dim3(8, 4), 256>>>(img_fc_w, edge_fc_w1 + (size_t)Hh*Hh,
                                     nullptr, p_Wc, Hh, Hh);
    gemm_kernel<<<dim3(1, 4), 256>>>(feat_img_2, img_fc_w, img_fc_b, p_fi2v,
                                     Bb, Hh);
    gemm_kernel<<<dim3(1, 4), 256>>>(feat_img_ssl, img_fc_w, img_fc_b, p_fsslv,
                                     Bb, Hh);
    biask_kernel<<<dim3(Bb, 4), 256>>>(edge_fc_b1, img_fc_b, edge_fc_w1);

    // fused maxpool + double GEMM + epilogue over active rows
    fuse_kernel<<<(ROWS + 63)/64, 256>>>(feat_img_1, edge_fc_w1, edge_fc_w2,
                                         edge_fc_b2, out);
}